// round 5
// baseline (speedup 1.0000x reference)
#include <cuda_runtime.h>
#include <math.h>

// Problem sizes (fixed by the dataset)
#define TT 512
#define BB 256
#define II 256
#define HH 256

// -------- scratch (device globals: allocation-free contract) --------
// Projections laid out [mat][t][b][h] so the scan reads contiguous slabs per step.
__device__ float g_xp[(size_t)3 * TT * BB * HH];   // 402 MB
// Transposed recurrent matrices: g_ut[m][k*HH + j] = U_m[j*HH + k]
__device__ float g_ut[3][HH * HH];

// ---------------------------------------------------------------
// Kernel 1: transpose U_z, U_a, U_h to k-major for coalesced GEMV
// ---------------------------------------------------------------
__global__ void transpose_U(const float* __restrict__ Uz,
                            const float* __restrict__ Ua,
                            const float* __restrict__ Uh) {
    int idx = blockIdx.x * blockDim.x + threadIdx.x;
    if (idx >= HH * HH) return;
    int j = idx / HH;           // row of U (output index)
    int k = idx % HH;           // col of U (contraction index) -> coalesced read
    g_ut[0][k * HH + j] = Uz[idx];
    g_ut[1][k * HH + j] = Ua[idx];
    g_ut[2][k * HH + j] = Uh[idx];
}

// ---------------------------------------------------------------
// Kernel 2: projection GEMM
//   out[mat][t][b][j] = sum_i x[b][t][i] * W_mat[j][i]
// A = x as [M=131072, K=256] (row = b*T + t), B = W_mat [j, i] (NT gemm)
// 128x128 tile, BK=16, 256 threads, 8x8 register micro-tile.
// N = 768 (3 matrices concatenated); a 128-wide tile never crosses a matrix.
// ---------------------------------------------------------------
__global__ __launch_bounds__(256) void proj_gemm(
    const float* __restrict__ x,
    const float* __restrict__ Wz,
    const float* __restrict__ Wa,
    const float* __restrict__ Wh) {
    constexpr int BM = 128, BN = 128, BK = 16;
    __shared__ float As[BK][BM];
    __shared__ float Bs[BK][BN];

    const int m0 = blockIdx.x * BM;
    const int n0 = blockIdx.y * BN;
    const int mat = n0 >> 8;          // which W matrix
    const int jb  = n0 & 255;         // column base within that matrix
    const float* W = (mat == 0) ? Wz : ((mat == 1) ? Wa : Wh);

    const int tid = threadIdx.x;
    const int tx = tid & 15;          // 16 col-groups
    const int ty = tid >> 4;          // 16 row-groups

    // load mapping: each thread loads 2x float4 of A and 2x float4 of B per k-tile
    const int lr = tid >> 2;          // 0..63
    const int lc = (tid & 3) * 4;     // 0,4,8,12

    float acc[8][8];
#pragma unroll
    for (int i = 0; i < 8; ++i)
#pragma unroll
        for (int jj = 0; jj < 8; ++jj) acc[i][jj] = 0.f;

    for (int k0 = 0; k0 < II; k0 += BK) {
        float4 a0 = *(const float4*)(x + (size_t)(m0 + lr)      * II + k0 + lc);
        float4 a1 = *(const float4*)(x + (size_t)(m0 + lr + 64) * II + k0 + lc);
        float4 b0 = *(const float4*)(W + (size_t)(jb + lr)      * II + k0 + lc);
        float4 b1 = *(const float4*)(W + (size_t)(jb + lr + 64) * II + k0 + lc);

        __syncthreads();   // previous tile fully consumed
        As[lc + 0][lr] = a0.x; As[lc + 1][lr] = a0.y; As[lc + 2][lr] = a0.z; As[lc + 3][lr] = a0.w;
        As[lc + 0][lr + 64] = a1.x; As[lc + 1][lr + 64] = a1.y; As[lc + 2][lr + 64] = a1.z; As[lc + 3][lr + 64] = a1.w;
        Bs[lc + 0][lr] = b0.x; Bs[lc + 1][lr] = b0.y; Bs[lc + 2][lr] = b0.z; Bs[lc + 3][lr] = b0.w;
        Bs[lc + 0][lr + 64] = b1.x; Bs[lc + 1][lr + 64] = b1.y; Bs[lc + 2][lr + 64] = b1.z; Bs[lc + 3][lr + 64] = b1.w;
        __syncthreads();

#pragma unroll
        for (int kk = 0; kk < BK; ++kk) {
            float4 ra0 = *(const float4*)&As[kk][ty * 8];
            float4 ra1 = *(const float4*)&As[kk][ty * 8 + 4];
            float4 rb0 = *(const float4*)&Bs[kk][tx * 8];
            float4 rb1 = *(const float4*)&Bs[kk][tx * 8 + 4];
            float ra[8] = {ra0.x, ra0.y, ra0.z, ra0.w, ra1.x, ra1.y, ra1.z, ra1.w};
            float rb[8] = {rb0.x, rb0.y, rb0.z, rb0.w, rb1.x, rb1.y, rb1.z, rb1.w};
#pragma unroll
            for (int i = 0; i < 8; ++i)
#pragma unroll
                for (int jj = 0; jj < 8; ++jj) acc[i][jj] += ra[i] * rb[jj];
        }
    }

    // epilogue: scatter rows to [t][b] layout (row = b*T + t)
#pragma unroll
    for (int i = 0; i < 8; ++i) {
        int row = m0 + ty * 8 + i;
        int b = row >> 9;             // T = 512
        int t = row & (TT - 1);
        float* o = g_xp + ((size_t)mat * TT + t) * (size_t)(BB * HH)
                        + (size_t)b * HH + jb + tx * 8;
        *(float4*)(o)     = make_float4(acc[i][0], acc[i][1], acc[i][2], acc[i][3]);
        *(float4*)(o + 4) = make_float4(acc[i][4], acc[i][5], acc[i][6], acc[i][7]);
    }
}

// ---------------------------------------------------------------
// Kernel 3: the recurrent scan.
// 128 CTAs x 256 threads. CTA c owns batch rows (2c, 2c+1).
// Thread j owns output column j of both rows. h kept in smem as float2.
// Softmax: exp without max-sub (|arg| <= ~4); division by the
// softmax sum deferred past the (linear) U_h GEMV.
// ---------------------------------------------------------------
__device__ __forceinline__ float sigmoidf_(float v) {
    return 1.0f / (1.0f + expf(-v));
}

__global__ __launch_bounds__(256) void scan_kernel(
    const float* __restrict__ bz,
    const float* __restrict__ va,
    const float* __restrict__ bh,
    float* __restrict__ out) {
    const int j  = threadIdx.x;
    const int b0 = blockIdx.x * 2;
    const int b1 = b0 + 1;

    __shared__ float2 hbuf[HH];     // (h[b0][k], h[b1][k])
    __shared__ float2 ehbuf[HH];    // (e*h)[b0][k], (e*h)[b1][k]
    __shared__ float2 red[8];

    const float bz_j = bz[j];
    const float va_j = va[j];
    const float bh_j = bh[j];

    const float* __restrict__ utz = &g_ut[0][0];
    const float* __restrict__ uta = &g_ut[1][0];
    const float* __restrict__ uth = &g_ut[2][0];

    const float* __restrict__ XZ = g_xp;
    const float* __restrict__ XA = g_xp + (size_t)TT * BB * HH;
    const float* __restrict__ XH = g_xp + (size_t)2 * TT * BB * HH;

    hbuf[j] = make_float2(0.f, 0.f);
    __syncthreads();

    float h0 = 0.f, h1 = 0.f;       // own-column hidden values (registers)

    const int lane = j & 31;
    const int warp = j >> 5;

    for (int t = 0; t < TT; ++t) {
        const size_t base = (size_t)t * (BB * HH);
        // prefetch per-step inputs early
        const float xz0 = XZ[base + (size_t)b0 * HH + j];
        const float xz1 = XZ[base + (size_t)b1 * HH + j];
        const float xa0 = XA[base + (size_t)b0 * HH + j];
        const float xa1 = XA[base + (size_t)b1 * HH + j];
        const float xh0 = XH[base + (size_t)b0 * HH + j];
        const float xh1 = XH[base + (size_t)b1 * HH + j];

        // ---- stage A: z pre-activation and attention pre-activation ----
        float za0 = 0.f, za1 = 0.f, aa0 = 0.f, aa1 = 0.f;
        {
            const float* pz = utz + j;
            const float* pa = uta + j;
#pragma unroll 8
            for (int k = 0; k < HH; ++k) {
                float2 hk = hbuf[k];
                float uz = pz[(size_t)k * HH];
                float ua = pa[(size_t)k * HH];
                za0 += hk.x * uz; za1 += hk.y * uz;
                aa0 += hk.x * ua; aa1 += hk.y * ua;
            }
        }
        const float z0 = sigmoidf_(xz0 + za0 + bz_j);
        const float z1 = sigmoidf_(xz1 + za1 + bz_j);
        const float e0 = expf(tanhf(xa0 + aa0) * va_j);
        const float e1 = expf(tanhf(xa1 + aa1) * va_j);

        // ---- block-wide sum of e over j (softmax denominator, 2 rows) ----
        float sx = e0, sy = e1;
#pragma unroll
        for (int o = 16; o > 0; o >>= 1) {
            sx += __shfl_xor_sync(0xffffffffu, sx, o);
            sy += __shfl_xor_sync(0xffffffffu, sy, o);
        }
        if (lane == 0) red[warp] = make_float2(sx, sy);
        __syncthreads();
        if (j < 32) {
            float2 v = (j < 8) ? red[j] : make_float2(0.f, 0.f);
#pragma unroll
            for (int o = 4; o > 0; o >>= 1) {
                v.x += __shfl_xor_sync(0xffffffffu, v.x, o);
                v.y += __shfl_xor_sync(0xffffffffu, v.y, o);
            }
            if (j == 0) red[0] = v;
        }
        __syncthreads();
        const float S0 = red[0].x;
        const float S1 = red[0].y;

        // unnormalized attended hidden: e * h (division by S deferred)
        ehbuf[j] = make_float2(e0 * h0, e1 * h1);
        __syncthreads();

        // ---- stage B: candidate pre-activation dot ----
        float d0 = 0.f, d1 = 0.f;
        {
            const float* ph = uth + j;
#pragma unroll 8
            for (int k = 0; k < HH; ++k) {
                float2 ek = ehbuf[k];
                float uh = ph[(size_t)k * HH];
                d0 += ek.x * uh; d1 += ek.y * uh;
            }
        }
        const float ht0 = tanhf(xh0 + d0 / S0 + bh_j);
        const float ht1 = tanhf(xh1 + d1 / S1 + bh_j);
        const float hn0 = h0 + z0 * (ht0 - h0);
        const float hn1 = h1 + z1 * (ht1 - h1);

        out[((size_t)b0 * TT + t) * HH + j] = hn0;
        out[((size_t)b1 * TT + t) * HH + j] = hn1;

        h0 = hn0; h1 = hn1;
        hbuf[j] = make_float2(hn0, hn1);
        __syncthreads();
    }

    // h_last appended after outputs [B,T,H]
    float* hl = out + (size_t)BB * TT * HH;
    hl[(size_t)b0 * HH + j] = h0;
    hl[(size_t)b1 * HH + j] = h1;
}

// ---------------------------------------------------------------
// kernel_launch: transpose -> projection GEMM -> scan (stream-ordered)
// Inputs (metadata order): x, W_z, U_z, b_z, W_a, U_a, v_a, W_h, U_h, b_h
// ---------------------------------------------------------------
extern "C" void kernel_launch(void* const* d_in, const int* in_sizes, int n_in,
                              void* d_out, int out_size) {
    const float* x  = (const float*)d_in[0];
    const float* Wz = (const float*)d_in[1];
    const float* Uz = (const float*)d_in[2];
    const float* bz = (const float*)d_in[3];
    const float* Wa = (const float*)d_in[4];
    const float* Ua = (const float*)d_in[5];
    const float* va = (const float*)d_in[6];
    const float* Wh = (const float*)d_in[7];
    const float* Uh = (const float*)d_in[8];
    const float* bh = (const float*)d_in[9];
    float* out = (float*)d_out;

    transpose_U<<<(HH * HH + 255) / 256, 256>>>(Uz, Ua, Uh);

    dim3 grid_g((BB * TT) / 128, (3 * HH) / 128);
    proj_gemm<<<grid_g, 256>>>(x, Wz, Wa, Wh);

    scan_kernel<<<BB / 2, 256>>>(bz, va, bh, out);
}

// round 6
// speedup vs baseline: 1.8457x; 1.8457x over previous
#include <cuda_runtime.h>
#include <math.h>

// Problem sizes (fixed by the dataset)
#define TT 512
#define BB 256
#define II 256
#define HH 256

// -------- scratch (device globals: allocation-free contract) --------
// Projections laid out [mat][t][b][h] so the scan reads contiguous slabs per step.
__device__ float g_xp[(size_t)3 * TT * BB * HH];   // 402 MB
// Re-blocked transposed recurrent matrices for vectorized GEMV:
//   g_u4[m][ ((k>>2)*HH + j)*4 + (k&3) ] = U_m[j*HH + k]
// i.e. thread owning column j loads float4 = U_m[j][4kk..4kk+3] contiguously,
// and a warp's 32 float4s cover 512 contiguous bytes.
__device__ float g_u4[3][HH * HH];

// ---------------------------------------------------------------
// Kernel 1: re-block U_z, U_a, U_h
// ---------------------------------------------------------------
__global__ void reblock_U(const float* __restrict__ Uz,
                          const float* __restrict__ Ua,
                          const float* __restrict__ Uh) {
    int idx = blockIdx.x * blockDim.x + threadIdx.x;
    if (idx >= HH * HH) return;
    int j = idx / HH;           // row of U (output index)
    int k = idx % HH;           // col of U (contraction index) -> coalesced read
    int dst = ((k >> 2) * HH + j) * 4 + (k & 3);
    g_u4[0][dst] = Uz[idx];
    g_u4[1][dst] = Ua[idx];
    g_u4[2][dst] = Uh[idx];
}

// ---------------------------------------------------------------
// Kernel 2: projection GEMM (unchanged from R5 — ~2ms, FFMA-bound)
//   out[mat][t][b][j] = sum_i x[b][t][i] * W_mat[j][i]
// ---------------------------------------------------------------
__global__ __launch_bounds__(256) void proj_gemm(
    const float* __restrict__ x,
    const float* __restrict__ Wz,
    const float* __restrict__ Wa,
    const float* __restrict__ Wh) {
    constexpr int BM = 128, BN = 128, BK = 16;
    __shared__ float As[BK][BM];
    __shared__ float Bs[BK][BN];

    const int m0 = blockIdx.x * BM;
    const int n0 = blockIdx.y * BN;
    const int mat = n0 >> 8;          // which W matrix
    const int jb  = n0 & 255;         // column base within that matrix
    const float* W = (mat == 0) ? Wz : ((mat == 1) ? Wa : Wh);

    const int tid = threadIdx.x;
    const int tx = tid & 15;          // 16 col-groups
    const int ty = tid >> 4;          // 16 row-groups

    const int lr = tid >> 2;          // 0..63
    const int lc = (tid & 3) * 4;     // 0,4,8,12

    float acc[8][8];
#pragma unroll
    for (int i = 0; i < 8; ++i)
#pragma unroll
        for (int jj = 0; jj < 8; ++jj) acc[i][jj] = 0.f;

    for (int k0 = 0; k0 < II; k0 += BK) {
        float4 a0 = *(const float4*)(x + (size_t)(m0 + lr)      * II + k0 + lc);
        float4 a1 = *(const float4*)(x + (size_t)(m0 + lr + 64) * II + k0 + lc);
        float4 b0 = *(const float4*)(W + (size_t)(jb + lr)      * II + k0 + lc);
        float4 b1 = *(const float4*)(W + (size_t)(jb + lr + 64) * II + k0 + lc);

        __syncthreads();
        As[lc + 0][lr] = a0.x; As[lc + 1][lr] = a0.y; As[lc + 2][lr] = a0.z; As[lc + 3][lr] = a0.w;
        As[lc + 0][lr + 64] = a1.x; As[lc + 1][lr + 64] = a1.y; As[lc + 2][lr + 64] = a1.z; As[lc + 3][lr + 64] = a1.w;
        Bs[lc + 0][lr] = b0.x; Bs[lc + 1][lr] = b0.y; Bs[lc + 2][lr] = b0.z; Bs[lc + 3][lr] = b0.w;
        Bs[lc + 0][lr + 64] = b1.x; Bs[lc + 1][lr + 64] = b1.y; Bs[lc + 2][lr + 64] = b1.z; Bs[lc + 3][lr + 64] = b1.w;
        __syncthreads();

#pragma unroll
        for (int kk = 0; kk < BK; ++kk) {
            float4 ra0 = *(const float4*)&As[kk][ty * 8];
            float4 ra1 = *(const float4*)&As[kk][ty * 8 + 4];
            float4 rb0 = *(const float4*)&Bs[kk][tx * 8];
            float4 rb1 = *(const float4*)&Bs[kk][tx * 8 + 4];
            float ra[8] = {ra0.x, ra0.y, ra0.z, ra0.w, ra1.x, ra1.y, ra1.z, ra1.w};
            float rb[8] = {rb0.x, rb0.y, rb0.z, rb0.w, rb1.x, rb1.y, rb1.z, rb1.w};
#pragma unroll
            for (int i = 0; i < 8; ++i)
#pragma unroll
                for (int jj = 0; jj < 8; ++jj) acc[i][jj] += ra[i] * rb[jj];
        }
    }

#pragma unroll
    for (int i = 0; i < 8; ++i) {
        int row = m0 + ty * 8 + i;
        int b = row >> 9;             // T = 512
        int t = row & (TT - 1);
        float* o = g_xp + ((size_t)mat * TT + t) * (size_t)(BB * HH)
                        + (size_t)b * HH + jb + tx * 8;
        *(float4*)(o)     = make_float4(acc[i][0], acc[i][1], acc[i][2], acc[i][3]);
        *(float4*)(o + 4) = make_float4(acc[i][4], acc[i][5], acc[i][6], acc[i][7]);
    }
}

// ---------------------------------------------------------------
// Kernel 3: recurrent scan. 64 CTAs x 256 threads.
// CTA c owns batch rows 4c..4c+3; thread j owns output column j (4 rows).
// U loads: LDG.128 (k-blocked layout). h / e*h in smem as float4 (4 rows).
// Softmax: exp w/o max-sub (|arg|<=~4); 1/S division deferred past U_h GEMV.
// ---------------------------------------------------------------
__global__ __launch_bounds__(256) void scan_kernel(
    const float* __restrict__ bz,
    const float* __restrict__ va,
    const float* __restrict__ bh,
    float* __restrict__ out) {
    const int j  = threadIdx.x;
    const int b0 = blockIdx.x * 4;

    __shared__ float4 hbuf[HH];     // h[b0+r][k] in component r
    __shared__ float4 ehbuf[HH];    // (e*h)[b0+r][k]
    __shared__ float4 red[8];

    const float bz_j = bz[j];
    const float va_j = va[j];
    const float bh_j = bh[j];

    const float4* __restrict__ uz4 = (const float4*)&g_u4[0][0];
    const float4* __restrict__ ua4 = (const float4*)&g_u4[1][0];
    const float4* __restrict__ uh4 = (const float4*)&g_u4[2][0];

    const float* __restrict__ XZ = g_xp;
    const float* __restrict__ XA = g_xp + (size_t)TT * BB * HH;
    const float* __restrict__ XH = g_xp + (size_t)2 * TT * BB * HH;

    hbuf[j] = make_float4(0.f, 0.f, 0.f, 0.f);
    __syncthreads();

    float h0 = 0.f, h1 = 0.f, h2 = 0.f, h3 = 0.f;   // own-column hidden values

    const int lane = j & 31;
    const int warp = j >> 5;

    for (int t = 0; t < TT; ++t) {
        const size_t base = (size_t)t * (BB * HH) + (size_t)b0 * HH + j;
        // per-step inputs (issued early; consumed after the GEMV)
        float xz[4], xa[4], xh[4];
#pragma unroll
        for (int r = 0; r < 4; ++r) {
            xz[r] = XZ[base + (size_t)r * HH];
            xa[r] = XA[base + (size_t)r * HH];
            xh[r] = XH[base + (size_t)r * HH];
        }

        // ---- stage A: z pre-activation & attention pre-activation ----
        float za0 = 0.f, za1 = 0.f, za2 = 0.f, za3 = 0.f;
        float aa0 = 0.f, aa1 = 0.f, aa2 = 0.f, aa3 = 0.f;
#pragma unroll 4
        for (int kk = 0; kk < HH / 4; ++kk) {
            float4 uz = uz4[kk * HH + j];      // U_z[j][4kk..4kk+3]
            float4 ua = ua4[kk * HH + j];
            float4 hk0 = hbuf[kk * 4 + 0];     // broadcast LDS.128
            float4 hk1 = hbuf[kk * 4 + 1];
            float4 hk2 = hbuf[kk * 4 + 2];
            float4 hk3 = hbuf[kk * 4 + 3];
            za0 += hk0.x * uz.x + hk1.x * uz.y + hk2.x * uz.z + hk3.x * uz.w;
            za1 += hk0.y * uz.x + hk1.y * uz.y + hk2.y * uz.z + hk3.y * uz.w;
            za2 += hk0.z * uz.x + hk1.z * uz.y + hk2.z * uz.z + hk3.z * uz.w;
            za3 += hk0.w * uz.x + hk1.w * uz.y + hk2.w * uz.z + hk3.w * uz.w;
            aa0 += hk0.x * ua.x + hk1.x * ua.y + hk2.x * ua.z + hk3.x * ua.w;
            aa1 += hk0.y * ua.x + hk1.y * ua.y + hk2.y * ua.z + hk3.y * ua.w;
            aa2 += hk0.z * ua.x + hk1.z * ua.y + hk2.z * ua.z + hk3.z * ua.w;
            aa3 += hk0.w * ua.x + hk1.w * ua.y + hk2.w * ua.z + hk3.w * ua.w;
        }
        float z0 = 1.f / (1.f + __expf(-(xz[0] + za0 + bz_j)));
        float z1 = 1.f / (1.f + __expf(-(xz[1] + za1 + bz_j)));
        float z2 = 1.f / (1.f + __expf(-(xz[2] + za2 + bz_j)));
        float z3 = 1.f / (1.f + __expf(-(xz[3] + za3 + bz_j)));
        float e0 = __expf(tanhf(xa[0] + aa0) * va_j);
        float e1 = __expf(tanhf(xa[1] + aa1) * va_j);
        float e2 = __expf(tanhf(xa[2] + aa2) * va_j);
        float e3 = __expf(tanhf(xa[3] + aa3) * va_j);

        // unnormalized attended hidden (division by S deferred past U_h)
        ehbuf[j] = make_float4(e0 * h0, e1 * h1, e2 * h2, e3 * h3);

        // ---- block-wide softmax denominators (4 rows at once) ----
        float sx = e0, sy = e1, sz = e2, sw = e3;
#pragma unroll
        for (int o = 16; o > 0; o >>= 1) {
            sx += __shfl_xor_sync(0xffffffffu, sx, o);
            sy += __shfl_xor_sync(0xffffffffu, sy, o);
            sz += __shfl_xor_sync(0xffffffffu, sz, o);
            sw += __shfl_xor_sync(0xffffffffu, sw, o);
        }
        if (lane == 0) red[warp] = make_float4(sx, sy, sz, sw);
        __syncthreads();                       // red + ehbuf visible
        if (j < 32) {
            float4 v = (j < 8) ? red[j] : make_float4(0.f, 0.f, 0.f, 0.f);
#pragma unroll
            for (int o = 4; o > 0; o >>= 1) {
                v.x += __shfl_xor_sync(0xffffffffu, v.x, o);
                v.y += __shfl_xor_sync(0xffffffffu, v.y, o);
                v.z += __shfl_xor_sync(0xffffffffu, v.z, o);
                v.w += __shfl_xor_sync(0xffffffffu, v.w, o);
            }
            if (j == 0) red[0] = v;
        }
        __syncthreads();
        const float4 S = red[0];

        // ---- stage B: candidate pre-activation dot ----
        float d0 = 0.f, d1 = 0.f, d2 = 0.f, d3 = 0.f;
#pragma unroll 4
        for (int kk = 0; kk < HH / 4; ++kk) {
            float4 uh = uh4[kk * HH + j];
            float4 ek0 = ehbuf[kk * 4 + 0];
            float4 ek1 = ehbuf[kk * 4 + 1];
            float4 ek2 = ehbuf[kk * 4 + 2];
            float4 ek3 = ehbuf[kk * 4 + 3];
            d0 += ek0.x * uh.x + ek1.x * uh.y + ek2.x * uh.z + ek3.x * uh.w;
            d1 += ek0.y * uh.x + ek1.y * uh.y + ek2.y * uh.z + ek3.y * uh.w;
            d2 += ek0.z * uh.x + ek1.z * uh.y + ek2.z * uh.z + ek3.z * uh.w;
            d3 += ek0.w * uh.x + ek1.w * uh.y + ek2.w * uh.z + ek3.w * uh.w;
        }
        float ht0 = tanhf(xh[0] + d0 / S.x + bh_j);
        float ht1 = tanhf(xh[1] + d1 / S.y + bh_j);
        float ht2 = tanhf(xh[2] + d2 / S.z + bh_j);
        float ht3 = tanhf(xh[3] + d3 / S.w + bh_j);
        float hn0 = h0 + z0 * (ht0 - h0);
        float hn1 = h1 + z1 * (ht1 - h1);
        float hn2 = h2 + z2 * (ht2 - h2);
        float hn3 = h3 + z3 * (ht3 - h3);

        out[((size_t)(b0 + 0) * TT + t) * HH + j] = hn0;
        out[((size_t)(b0 + 1) * TT + t) * HH + j] = hn1;
        out[((size_t)(b0 + 2) * TT + t) * HH + j] = hn2;
        out[((size_t)(b0 + 3) * TT + t) * HH + j] = hn3;

        h0 = hn0; h1 = hn1; h2 = hn2; h3 = hn3;
        hbuf[j] = make_float4(hn0, hn1, hn2, hn3);
        __syncthreads();
    }

    // h_last appended after outputs [B,T,H]
    float* hl = out + (size_t)BB * TT * HH;
    hl[(size_t)(b0 + 0) * HH + j] = h0;
    hl[(size_t)(b0 + 1) * HH + j] = h1;
    hl[(size_t)(b0 + 2) * HH + j] = h2;
    hl[(size_t)(b0 + 3) * HH + j] = h3;
}

// ---------------------------------------------------------------
// kernel_launch: reblock -> projection GEMM -> scan (stream-ordered)
// Inputs (metadata order): x, W_z, U_z, b_z, W_a, U_a, v_a, W_h, U_h, b_h
// ---------------------------------------------------------------
extern "C" void kernel_launch(void* const* d_in, const int* in_sizes, int n_in,
                              void* d_out, int out_size) {
    const float* x  = (const float*)d_in[0];
    const float* Wz = (const float*)d_in[1];
    const float* Uz = (const float*)d_in[2];
    const float* bz = (const float*)d_in[3];
    const float* Wa = (const float*)d_in[4];
    const float* Ua = (const float*)d_in[5];
    const float* va = (const float*)d_in[6];
    const float* Wh = (const float*)d_in[7];
    const float* Uh = (const float*)d_in[8];
    const float* bh = (const float*)d_in[9];
    float* out = (float*)d_out;

    reblock_U<<<(HH * HH + 255) / 256, 256>>>(Uz, Ua, Uh);

    dim3 grid_g((BB * TT) / 128, (3 * HH) / 128);
    proj_gemm<<<grid_g, 256>>>(x, Wz, Wa, Wh);

    scan_kernel<<<BB / 4, 256>>>(bz, va, bh, out);
}

// round 7
// speedup vs baseline: 3.0051x; 1.6282x over previous
#include <cuda_runtime.h>
#include <math.h>

// Problem sizes (fixed by the dataset)
#define TT 512
#define BB 256
#define II 256
#define HH 256
#define NG 32          // batch groups (8 rows each)
#define NSL 4          // k-slices per group (64 k each)

// -------- scratch (device globals: allocation-free contract) --------
__device__ float g_xp[(size_t)3 * TT * BB * HH];     // projections [mat][t][b][h]
// k-blocked transposed U: g_u4[m][((k>>2)*HH + j)*4 + (k&3)] = U_m[j*HH + k]
__device__ float g_u4[3][HH * HH];
// cross-CTA partial buffers (single-buffered; safety by flag protocol)
__device__ float g_pA[NG * NSL * HH * 16];           // za[8], aa[8] per (cta, j)
__device__ float g_pB[NG * NSL * HH * 8];            // d[8] per (cta, j)
__device__ float g_pS[NG * NSL * 8];                 // partial softmax sums per row
__device__ unsigned int g_fl[NG * NSL * TT * 2];     // one flag per (cta, step, exchange)

// ---------------- asm helpers ----------------
__device__ __forceinline__ void ffma2(unsigned long long& d, unsigned long long a,
                                      unsigned long long b) {
    asm("fma.rn.f32x2 %0, %1, %2, %0;" : "+l"(d) : "l"(a), "l"(b));
}
__device__ __forceinline__ unsigned long long fdup(float v) {
    unsigned long long r; unsigned int u = __float_as_uint(v);
    asm("mov.b64 %0, {%1, %1};" : "=l"(r) : "r"(u));
    return r;
}
__device__ __forceinline__ float ffold(unsigned long long v) {
    return __uint_as_float((unsigned int)(v & 0xffffffffull)) +
           __uint_as_float((unsigned int)(v >> 32));
}
__device__ __forceinline__ void st_release_u32(unsigned int* p, unsigned int v) {
    asm volatile("st.release.gpu.global.u32 [%0], %1;" :: "l"(p), "r"(v) : "memory");
}
__device__ __forceinline__ unsigned int ld_acquire_u32(const unsigned int* p) {
    unsigned int v;
    asm volatile("ld.acquire.gpu.global.u32 %0, [%1];" : "=r"(v) : "l"(p) : "memory");
    return v;
}

// ---------------------------------------------------------------
// Kernel 0: zero the flags (runs first on every graph replay)
// ---------------------------------------------------------------
__global__ void zero_flags() {
    int i = blockIdx.x * blockDim.x + threadIdx.x;
    if (i < NG * NSL * TT * 2) g_fl[i] = 0u;
}

// ---------------------------------------------------------------
// Kernel 1: re-block U_z, U_a, U_h into k-quad layout
// ---------------------------------------------------------------
__global__ void reblock_U(const float* __restrict__ Uz,
                          const float* __restrict__ Ua,
                          const float* __restrict__ Uh) {
    int idx = blockIdx.x * blockDim.x + threadIdx.x;
    if (idx >= HH * HH) return;
    int j = idx / HH;
    int k = idx % HH;
    int dst = ((k >> 2) * HH + j) * 4 + (k & 3);
    g_u4[0][dst] = Uz[idx];
    g_u4[1][dst] = Ua[idx];
    g_u4[2][dst] = Uh[idx];
}

// ---------------------------------------------------------------
// Kernel 2: projection GEMM with FFMA2 (dup-A x paired-B)
//   g_xp[mat][t][b][j] = sum_i x[b][t][i] * W_mat[j][i]
// ---------------------------------------------------------------
__global__ __launch_bounds__(256) void proj_gemm(
    const float* __restrict__ x,
    const float* __restrict__ Wz,
    const float* __restrict__ Wa,
    const float* __restrict__ Wh) {
    constexpr int BM = 128, BN = 128, BK = 16;
    __shared__ float As[BK][BM];
    __shared__ float Bs[BK][BN];

    const int m0 = blockIdx.x * BM;
    const int n0 = blockIdx.y * BN;
    const int mat = n0 >> 8;
    const int jb  = n0 & 255;
    const float* W = (mat == 0) ? Wz : ((mat == 1) ? Wa : Wh);

    const int tid = threadIdx.x;
    const int tx = tid & 15;
    const int ty = tid >> 4;
    const int lr = tid >> 2;
    const int lc = (tid & 3) * 4;

    unsigned long long acc2[8][4];
#pragma unroll
    for (int i = 0; i < 8; ++i)
#pragma unroll
        for (int p = 0; p < 4; ++p) acc2[i][p] = 0ull;

    for (int k0 = 0; k0 < II; k0 += BK) {
        float4 a0 = *(const float4*)(x + (size_t)(m0 + lr)      * II + k0 + lc);
        float4 a1 = *(const float4*)(x + (size_t)(m0 + lr + 64) * II + k0 + lc);
        float4 b0 = *(const float4*)(W + (size_t)(jb + lr)      * II + k0 + lc);
        float4 b1 = *(const float4*)(W + (size_t)(jb + lr + 64) * II + k0 + lc);

        __syncthreads();
        As[lc + 0][lr] = a0.x; As[lc + 1][lr] = a0.y; As[lc + 2][lr] = a0.z; As[lc + 3][lr] = a0.w;
        As[lc + 0][lr + 64] = a1.x; As[lc + 1][lr + 64] = a1.y; As[lc + 2][lr + 64] = a1.z; As[lc + 3][lr + 64] = a1.w;
        Bs[lc + 0][lr] = b0.x; Bs[lc + 1][lr] = b0.y; Bs[lc + 2][lr] = b0.z; Bs[lc + 3][lr] = b0.w;
        Bs[lc + 0][lr + 64] = b1.x; Bs[lc + 1][lr + 64] = b1.y; Bs[lc + 2][lr + 64] = b1.z; Bs[lc + 3][lr + 64] = b1.w;
        __syncthreads();

#pragma unroll
        for (int kk = 0; kk < BK; ++kk) {
            float4 ra0 = *(const float4*)&As[kk][ty * 8];
            float4 ra1 = *(const float4*)&As[kk][ty * 8 + 4];
            ulonglong2 rb0 = *(const ulonglong2*)&Bs[kk][tx * 8];
            ulonglong2 rb1 = *(const ulonglong2*)&Bs[kk][tx * 8 + 4];
            unsigned long long pa[8];
            pa[0] = fdup(ra0.x); pa[1] = fdup(ra0.y); pa[2] = fdup(ra0.z); pa[3] = fdup(ra0.w);
            pa[4] = fdup(ra1.x); pa[5] = fdup(ra1.y); pa[6] = fdup(ra1.z); pa[7] = fdup(ra1.w);
#pragma unroll
            for (int i = 0; i < 8; ++i) {
                ffma2(acc2[i][0], pa[i], rb0.x);
                ffma2(acc2[i][1], pa[i], rb0.y);
                ffma2(acc2[i][2], pa[i], rb1.x);
                ffma2(acc2[i][3], pa[i], rb1.y);
            }
        }
    }

#pragma unroll
    for (int i = 0; i < 8; ++i) {
        int row = m0 + ty * 8 + i;
        int b = row >> 9;             // T = 512
        int t = row & (TT - 1);
        float* o = g_xp + ((size_t)mat * TT + t) * (size_t)(BB * HH)
                        + (size_t)b * HH + jb + tx * 8;
        *(float4*)(o)     = *(const float4*)&acc2[i][0];   // (c0,c1,c2,c3)
        *(float4*)(o + 4) = *(const float4*)&acc2[i][2];   // (c4,c5,c6,c7)
    }
}

// ---------------------------------------------------------------
// Kernel 3: recurrent scan, 128 CTAs (32 groups x 4 k-slices).
// Each CTA: 8 batch rows, k-slice of 64, U slice resident in smem (192KB).
// GEMV partials exchanged through L2 with release/acquire flags.
// Each CTA finalizes columns j in its own k-slice (so h stays local).
// ---------------------------------------------------------------
__device__ __forceinline__ float sigmoidf_(float v) {
    return 1.0f / (1.0f + __expf(-v));
}

__global__ __launch_bounds__(256, 1) void scan_kernel(
    const float* __restrict__ bz,
    const float* __restrict__ va,
    const float* __restrict__ bh,
    float* __restrict__ out) {
    extern __shared__ float sm[];
    float* sU  = sm;            // [3][16 kq][256 j][4]  = 49152 floats (192KB)
    float* hs  = sm + 49152;    // [8 rows][64 k-local]
    float* ehs = sm + 49664;    // [8 rows][64 k-local]
    float* es  = sm + 50176;    // [8 rows][64 j-local]

    const int tid = threadIdx.x;
    const int g = blockIdx.x >> 2;        // batch group
    const int r = blockIdx.x & 3;         // k-slice index
    const int b0 = g * 8;

    // ---- load U slice into smem (contiguous 64KB per matrix) ----
    {
        const float4* src = (const float4*)(&g_u4[0][0]);
        float4* dst = (float4*)sU;
        for (int i = tid; i < 3 * 4096; i += 256) {
            int m = i >> 12;
            int o = i & 4095;
            dst[i] = src[m * 16384 + r * 4096 + o];
        }
    }
    if (tid < 128) ((float4*)hs)[tid] = make_float4(0.f, 0.f, 0.f, 0.f);
    __syncthreads();

    const int jj = tid & 63;
    const int rh = tid >> 6;              // 0..3 -> rows 2rh, 2rh+1
    const int jg = r * 64 + jj;           // global column this CTA finalizes
    const float bzv = bz[jg], vav = va[jg], bhv = bh[jg];

    float h0 = 0.f, h1 = 0.f;             // h for rows (2rh, 2rh+1), column jg

    const float* __restrict__ XZ = g_xp;
    const float* __restrict__ XA = g_xp + (size_t)TT * BB * HH;
    const float* __restrict__ XH = g_xp + (size_t)2 * TT * BB * HH;

    float* pA_my = g_pA + (size_t)(g * 4 + r) * HH * 16;
    float* pB_my = g_pB + (size_t)(g * 4 + r) * HH * 8;
    unsigned int* flbase = g_fl + (size_t)(g * 4) * (TT * 2);

    const ulonglong2* Uz2 = (const ulonglong2*)(sU);
    const ulonglong2* Ua2 = (const ulonglong2*)(sU + 16384);
    const ulonglong2* Uh2 = (const ulonglong2*)(sU + 32768);

    for (int t = 0; t < TT; ++t) {
        // prefetch per-step x values for finalize (consumed after GEMVs)
        const size_t xb = (size_t)t * (BB * HH);
        const size_t xo0 = xb + (size_t)(b0 + 2 * rh) * HH + jg;
        const size_t xo1 = xo0 + HH;
        const float xz0 = XZ[xo0], xz1 = XZ[xo1];
        const float xa0 = XA[xo0], xa1 = XA[xo1];
        const float xh0 = XH[xo0], xh1 = XH[xo1];

        // ======== stage A: partial GEMVs over this CTA's k-slice, all columns ========
        unsigned long long za[8], aa[8];
#pragma unroll
        for (int q = 0; q < 8; ++q) { za[q] = 0ull; aa[q] = 0ull; }
#pragma unroll 4
        for (int kq = 0; kq < 16; ++kq) {
            ulonglong2 uz = Uz2[kq * 256 + tid];
            ulonglong2 ua = Ua2[kq * 256 + tid];
#pragma unroll
            for (int row = 0; row < 8; ++row) {
                ulonglong2 hk = *(const ulonglong2*)(hs + row * 64 + kq * 4);
                ffma2(za[row], hk.x, uz.x); ffma2(za[row], hk.y, uz.y);
                ffma2(aa[row], hk.x, ua.x); ffma2(aa[row], hk.y, ua.y);
            }
        }
        {
            float pout[16];
#pragma unroll
            for (int row = 0; row < 8; ++row) {
                pout[row]     = ffold(za[row]);
                pout[8 + row] = ffold(aa[row]);
            }
            float* wp = pA_my + tid * 16;
            *(float4*)(wp + 0)  = *(const float4*)&pout[0];
            *(float4*)(wp + 4)  = *(const float4*)&pout[4];
            *(float4*)(wp + 8)  = *(const float4*)&pout[8];
            *(float4*)(wp + 12) = *(const float4*)&pout[12];
        }
        __threadfence();
        __syncthreads();
        if (tid == 0) st_release_u32(&flbase[r * (TT * 2) + 2 * t], 1u);
        if (tid < NSL && tid != r) {
            const unsigned int* f = &flbase[tid * (TT * 2) + 2 * t];
            while (ld_acquire_u32(f) == 0u) { }
        }
        __syncthreads();

        // ======== stage A finalize: own slice columns, 2 rows per thread ========
        float za0 = 0.f, za1 = 0.f, aa0 = 0.f, aa1 = 0.f;
#pragma unroll
        for (int c = 0; c < 4; ++c) {
            const float2* p = (const float2*)(g_pA + ((size_t)(g * 4 + c) * HH + jg) * 16);
            float2 vz = p[rh];
            float2 vaa = p[4 + rh];
            za0 += vz.x; za1 += vz.y; aa0 += vaa.x; aa1 += vaa.y;
        }
        const float z0 = sigmoidf_(xz0 + za0 + bzv);
        const float z1 = sigmoidf_(xz1 + za1 + bzv);
        const float e0 = __expf(tanhf(xa0 + aa0) * vav);
        const float e1 = __expf(tanhf(xa1 + aa1) * vav);
        es[(2 * rh) * 64 + jj]      = e0;
        es[(2 * rh + 1) * 64 + jj]  = e1;
        ehs[(2 * rh) * 64 + jj]     = e0 * h0;
        ehs[(2 * rh + 1) * 64 + jj] = e1 * h1;
        __syncthreads();

        // partial softmax sums: warp w sums row w over the 64 local columns
        {
            const int w = tid >> 5, lane = tid & 31;
            float se = es[w * 64 + lane] + es[w * 64 + 32 + lane];
#pragma unroll
            for (int o = 16; o > 0; o >>= 1) se += __shfl_xor_sync(0xffffffffu, se, o);
            if (lane == 0) g_pS[(g * 4 + r) * 8 + w] = se;
        }

        // ======== stage B: partial GEMV of e*h over k-slice, all columns ========
        unsigned long long dd[8];
#pragma unroll
        for (int q = 0; q < 8; ++q) dd[q] = 0ull;
#pragma unroll 4
        for (int kq = 0; kq < 16; ++kq) {
            ulonglong2 uh = Uh2[kq * 256 + tid];
#pragma unroll
            for (int row = 0; row < 8; ++row) {
                ulonglong2 ek = *(const ulonglong2*)(ehs + row * 64 + kq * 4);
                ffma2(dd[row], ek.x, uh.x); ffma2(dd[row], ek.y, uh.y);
            }
        }
        {
            float pout[8];
#pragma unroll
            for (int row = 0; row < 8; ++row) pout[row] = ffold(dd[row]);
            float* wp = pB_my + tid * 8;
            *(float4*)(wp + 0) = *(const float4*)&pout[0];
            *(float4*)(wp + 4) = *(const float4*)&pout[4];
        }
        __threadfence();
        __syncthreads();
        if (tid == 0) st_release_u32(&flbase[r * (TT * 2) + 2 * t + 1], 1u);
        if (tid < NSL && tid != r) {
            const unsigned int* f = &flbase[tid * (TT * 2) + 2 * t + 1];
            while (ld_acquire_u32(f) == 0u) { }
        }
        __syncthreads();

        // ======== stage B finalize: candidate, gate, h update ========
        float d0 = 0.f, d1 = 0.f, S0 = 0.f, S1 = 0.f;
#pragma unroll
        for (int c = 0; c < 4; ++c) {
            const float2* q = (const float2*)(g_pB + ((size_t)(g * 4 + c) * HH + jg) * 8);
            float2 v = q[rh];
            d0 += v.x; d1 += v.y;
            const float2* s = (const float2*)(g_pS + (g * 4 + c) * 8);
            float2 sv = s[rh];
            S0 += sv.x; S1 += sv.y;
        }
        const float ht0 = tanhf(xh0 + d0 / S0 + bhv);
        const float ht1 = tanhf(xh1 + d1 / S1 + bhv);
        const float hn0 = h0 + z0 * (ht0 - h0);
        const float hn1 = h1 + z1 * (ht1 - h1);

        out[((size_t)(b0 + 2 * rh) * TT + t) * HH + jg]     = hn0;
        out[((size_t)(b0 + 2 * rh + 1) * TT + t) * HH + jg] = hn1;

        h0 = hn0; h1 = hn1;
        hs[(2 * rh) * 64 + jj]     = hn0;
        hs[(2 * rh + 1) * 64 + jj] = hn1;
        __syncthreads();
    }

    // h_last appended after outputs [B,T,H]
    float* hl = out + (size_t)BB * TT * HH;
    hl[(size_t)(b0 + 2 * rh) * HH + jg]     = h0;
    hl[(size_t)(b0 + 2 * rh + 1) * HH + jg] = h1;
}

// ---------------------------------------------------------------
// kernel_launch: zero flags -> reblock -> GEMM -> scan
// Inputs: x, W_z, U_z, b_z, W_a, U_a, v_a, W_h, U_h, b_h
// ---------------------------------------------------------------
extern "C" void kernel_launch(void* const* d_in, const int* in_sizes, int n_in,
                              void* d_out, int out_size) {
    const float* x  = (const float*)d_in[0];
    const float* Wz = (const float*)d_in[1];
    const float* Uz = (const float*)d_in[2];
    const float* bz = (const float*)d_in[3];
    const float* Wa = (const float*)d_in[4];
    const float* Ua = (const float*)d_in[5];
    const float* va = (const float*)d_in[6];
    const float* Wh = (const float*)d_in[7];
    const float* Uh = (const float*)d_in[8];
    const float* bh = (const float*)d_in[9];
    float* out = (float*)d_out;

    static bool attr_set = false;
    if (!attr_set) {
        cudaFuncSetAttribute(scan_kernel, cudaFuncAttributeMaxDynamicSharedMemorySize,
                             50688 * 4);
        attr_set = true;
    }

    zero_flags<<<(NG * NSL * TT * 2 + 255) / 256, 256>>>();
    reblock_U<<<(HH * HH + 255) / 256, 256>>>(Uz, Ua, Uh);

    dim3 grid_g((BB * TT) / 128, (3 * HH) / 128);
    proj_gemm<<<grid_g, 256>>>(x, Wz, Wa, Wh);

    scan_kernel<<<NG * NSL, 256, 50688 * 4>>>(bz, va, bh, out);
}

// round 8
// speedup vs baseline: 3.3575x; 1.1173x over previous
#include <cuda_runtime.h>
#include <math.h>

// Problem sizes (fixed by the dataset)
#define TT 512
#define BB 256
#define II 256
#define HH 256
#define NG 32          // batch groups (8 rows each)
#define NSL 4          // k-slices per group (64 k each)

// -------- scratch (device globals: allocation-free contract) --------
__device__ float g_xp[(size_t)3 * TT * BB * HH];     // projections [mat][t][b][h]
// k-blocked transposed U: g_u4[m][((k>>2)*HH + j)*4 + (k&3)] = U_m[j*HH + k]
__device__ float g_u4[3][HH * HH];
// cross-CTA partial buffers, layout [subslice][value][j] for coalescing
//   subslice = (g*4 + r)*2 + khalf
__device__ float g_pA[NG * NSL * 2 * 16 * HH];       // values: za[8 rows], aa[8 rows]
__device__ float g_pB[NG * NSL * 2 * 8 * HH];        // values: d[8 rows]
__device__ float g_pS[NG * NSL * 8];                 // partial softmax sums per row
__device__ unsigned int g_fl[NG * NSL * TT * 2];     // flag per (cta, step, stage)

// ---------------- asm helpers ----------------
__device__ __forceinline__ void ffma2(unsigned long long& d, unsigned long long a,
                                      unsigned long long b) {
    asm("fma.rn.f32x2 %0, %1, %2, %0;" : "+l"(d) : "l"(a), "l"(b));
}
__device__ __forceinline__ unsigned long long fdup(float v) {
    unsigned long long r; unsigned int u = __float_as_uint(v);
    asm("mov.b64 %0, {%1, %1};" : "=l"(r) : "r"(u));
    return r;
}
__device__ __forceinline__ float ffold(unsigned long long v) {
    return __uint_as_float((unsigned int)(v & 0xffffffffull)) +
           __uint_as_float((unsigned int)(v >> 32));
}
__device__ __forceinline__ void st_release_u32(unsigned int* p, unsigned int v) {
    asm volatile("st.release.gpu.global.u32 [%0], %1;" :: "l"(p), "r"(v) : "memory");
}
__device__ __forceinline__ unsigned int ld_acquire_u32(const unsigned int* p) {
    unsigned int v;
    asm volatile("ld.acquire.gpu.global.u32 %0, [%1];" : "=r"(v) : "l"(p) : "memory");
    return v;
}

// ---------------------------------------------------------------
// Kernel 0: zero the flags (runs first on every graph replay)
// ---------------------------------------------------------------
__global__ void zero_flags() {
    int i = blockIdx.x * blockDim.x + threadIdx.x;
    if (i < NG * NSL * TT * 2) g_fl[i] = 0u;
}

// ---------------------------------------------------------------
// Kernel 1: re-block U_z, U_a, U_h into k-quad layout
// ---------------------------------------------------------------
__global__ void reblock_U(const float* __restrict__ Uz,
                          const float* __restrict__ Ua,
                          const float* __restrict__ Uh) {
    int idx = blockIdx.x * blockDim.x + threadIdx.x;
    if (idx >= HH * HH) return;
    int j = idx / HH;
    int k = idx % HH;
    int dst = ((k >> 2) * HH + j) * 4 + (k & 3);
    g_u4[0][dst] = Uz[idx];
    g_u4[1][dst] = Ua[idx];
    g_u4[2][dst] = Uh[idx];
}

// ---------------------------------------------------------------
// Kernel 2: projection GEMM with FFMA2 (dup-A x paired-B)
//   g_xp[mat][t][b][j] = sum_i x[b][t][i] * W_mat[j][i]
// ---------------------------------------------------------------
__global__ __launch_bounds__(256) void proj_gemm(
    const float* __restrict__ x,
    const float* __restrict__ Wz,
    const float* __restrict__ Wa,
    const float* __restrict__ Wh) {
    constexpr int BM = 128, BN = 128, BK = 16;
    __shared__ float As[BK][BM];
    __shared__ float Bs[BK][BN];

    const int m0 = blockIdx.x * BM;
    const int n0 = blockIdx.y * BN;
    const int mat = n0 >> 8;
    const int jb  = n0 & 255;
    const float* W = (mat == 0) ? Wz : ((mat == 1) ? Wa : Wh);

    const int tid = threadIdx.x;
    const int tx = tid & 15;
    const int ty = tid >> 4;
    const int lr = tid >> 2;
    const int lc = (tid & 3) * 4;

    unsigned long long acc2[8][4];
#pragma unroll
    for (int i = 0; i < 8; ++i)
#pragma unroll
        for (int p = 0; p < 4; ++p) acc2[i][p] = 0ull;

    for (int k0 = 0; k0 < II; k0 += BK) {
        float4 a0 = *(const float4*)(x + (size_t)(m0 + lr)      * II + k0 + lc);
        float4 a1 = *(const float4*)(x + (size_t)(m0 + lr + 64) * II + k0 + lc);
        float4 b0 = *(const float4*)(W + (size_t)(jb + lr)      * II + k0 + lc);
        float4 b1 = *(const float4*)(W + (size_t)(jb + lr + 64) * II + k0 + lc);

        __syncthreads();
        As[lc + 0][lr] = a0.x; As[lc + 1][lr] = a0.y; As[lc + 2][lr] = a0.z; As[lc + 3][lr] = a0.w;
        As[lc + 0][lr + 64] = a1.x; As[lc + 1][lr + 64] = a1.y; As[lc + 2][lr + 64] = a1.z; As[lc + 3][lr + 64] = a1.w;
        Bs[lc + 0][lr] = b0.x; Bs[lc + 1][lr] = b0.y; Bs[lc + 2][lr] = b0.z; Bs[lc + 3][lr] = b0.w;
        Bs[lc + 0][lr + 64] = b1.x; Bs[lc + 1][lr + 64] = b1.y; Bs[lc + 2][lr + 64] = b1.z; Bs[lc + 3][lr + 64] = b1.w;
        __syncthreads();

#pragma unroll
        for (int kk = 0; kk < BK; ++kk) {
            float4 ra0 = *(const float4*)&As[kk][ty * 8];
            float4 ra1 = *(const float4*)&As[kk][ty * 8 + 4];
            ulonglong2 rb0 = *(const ulonglong2*)&Bs[kk][tx * 8];
            ulonglong2 rb1 = *(const ulonglong2*)&Bs[kk][tx * 8 + 4];
            unsigned long long pa[8];
            pa[0] = fdup(ra0.x); pa[1] = fdup(ra0.y); pa[2] = fdup(ra0.z); pa[3] = fdup(ra0.w);
            pa[4] = fdup(ra1.x); pa[5] = fdup(ra1.y); pa[6] = fdup(ra1.z); pa[7] = fdup(ra1.w);
#pragma unroll
            for (int i = 0; i < 8; ++i) {
                ffma2(acc2[i][0], pa[i], rb0.x);
                ffma2(acc2[i][1], pa[i], rb0.y);
                ffma2(acc2[i][2], pa[i], rb1.x);
                ffma2(acc2[i][3], pa[i], rb1.y);
            }
        }
    }

#pragma unroll
    for (int i = 0; i < 8; ++i) {
        int row = m0 + ty * 8 + i;
        int b = row >> 9;             // T = 512
        int t = row & (TT - 1);
        float* o = g_xp + ((size_t)mat * TT + t) * (size_t)(BB * HH)
                        + (size_t)b * HH + jb + tx * 8;
        *(float4*)(o)     = *(const float4*)&acc2[i][0];
        *(float4*)(o + 4) = *(const float4*)&acc2[i][2];
    }
}

// ---------------------------------------------------------------
// Kernel 3: recurrent scan, 128 CTAs (32 groups x 4 k-slices),
// 512 threads each (16 warps -> 4 per SMSP for latency hiding).
// GEMV stages: thread = (j in 0..255, khalf in 0..1), 8 rows each.
// Finalize:    thread = (jj in 0..63, row in 0..7), 1 state elem each.
// ---------------------------------------------------------------
__device__ __forceinline__ float sigmoidf_(float v) {
    return 1.0f / (1.0f + __expf(-v));
}

__global__ __launch_bounds__(512, 1) void scan_kernel(
    const float* __restrict__ bz,
    const float* __restrict__ va,
    const float* __restrict__ bh,
    float* __restrict__ out) {
    extern __shared__ float sm[];
    float* sU  = sm;            // [3][16 kq][256 j][4] = 49152 floats (192KB)
    float* hs  = sm + 49152;    // [8 rows][64 k-local]
    float* ehs = sm + 49664;    // [8 rows][64 k-local]
    float* es  = sm + 50176;    // [8 rows][64 j-local]

    const int tid = threadIdx.x;
    const int g = blockIdx.x >> 2;        // batch group
    const int r = blockIdx.x & 3;         // k-slice index
    const int b0 = g * 8;

    // ---- load U slice into smem ----
    {
        const float4* src = (const float4*)(&g_u4[0][0]);
        float4* dst = (float4*)sU;
        for (int i = tid; i < 3 * 4096; i += 512) {
            int m = i >> 12;
            int o = i & 4095;
            dst[i] = src[m * 16384 + r * 4096 + o];
        }
    }
    if (tid < 128) ((float4*)hs)[tid] = make_float4(0.f, 0.f, 0.f, 0.f);
    __syncthreads();

    // GEMV-stage identity
    const int jq    = tid & 255;          // column for partial GEMV
    const int khalf = tid >> 8;           // which half of the 64-k slice
    // finalize identity
    const int jj  = tid & 63;
    const int row = tid >> 6;             // 0..7
    const int jg  = r * 64 + jj;          // global column this thread finalizes
    const float bzv = bz[jg], vav = va[jg], bhv = bh[jg];

    float h = 0.f;                         // state for (b0+row, jg)

    const float* __restrict__ XZ = g_xp;
    const float* __restrict__ XA = g_xp + (size_t)TT * BB * HH;
    const float* __restrict__ XH = g_xp + (size_t)2 * TT * BB * HH;

    // my partial-output bases (layout [value][j])
    float* pA_my = g_pA + (size_t)((g * 4 + r) * 2 + khalf) * (16 * HH);
    float* pB_my = g_pB + (size_t)((g * 4 + r) * 2 + khalf) * (8 * HH);
    unsigned int* flbase = g_fl + (size_t)(g * 4) * (TT * 2);

    const ulonglong2* Uz2 = (const ulonglong2*)(sU);
    const ulonglong2* Ua2 = (const ulonglong2*)(sU + 16384);
    const ulonglong2* Uh2 = (const ulonglong2*)(sU + 32768);
    const int kqb = khalf * 8;            // base kq for this thread

    for (int t = 0; t < TT; ++t) {
        // per-step x values for my (row, jg)
        const size_t xo = (size_t)t * (BB * HH) + (size_t)(b0 + row) * HH + jg;
        const float xz = XZ[xo];
        const float xa = XA[xo];
        const float xh = XH[xo];

        // ======== stage A: partial GEMVs (za, aa) over my k quarter ========
        unsigned long long za[8], aa[8];
#pragma unroll
        for (int q = 0; q < 8; ++q) { za[q] = 0ull; aa[q] = 0ull; }
#pragma unroll
        for (int q = 0; q < 8; ++q) {
            ulonglong2 uz = Uz2[(kqb + q) * 256 + jq];
            ulonglong2 ua = Ua2[(kqb + q) * 256 + jq];
            const float* hb = hs + khalf * 32 + q * 4;
#pragma unroll
            for (int rr = 0; rr < 8; ++rr) {
                ulonglong2 hk = *(const ulonglong2*)(hb + rr * 64);
                ffma2(za[rr], hk.x, uz.x); ffma2(za[rr], hk.y, uz.y);
                ffma2(aa[rr], hk.x, ua.x); ffma2(aa[rr], hk.y, ua.y);
            }
        }
#pragma unroll
        for (int rr = 0; rr < 8; ++rr) {
            pA_my[rr * HH + jq]       = ffold(za[rr]);
            pA_my[(8 + rr) * HH + jq] = ffold(aa[rr]);
        }
        __syncthreads();
        if (tid == 0) st_release_u32(&flbase[r * (TT * 2) + 2 * t], 1u);
        if (tid < NSL && tid != r) {
            const unsigned int* f = &flbase[tid * (TT * 2) + 2 * t];
            while (ld_acquire_u32(f) == 0u) { }
        }
        __syncthreads();

        // ======== stage A finalize: my (row, jg) ========
        float zaS = 0.f, aaS = 0.f;
#pragma unroll
        for (int c = 0; c < 8; ++c) {     // 4 slices x 2 khalf
            const float* p = g_pA + (size_t)((g * 4) * 2 + c) * (16 * HH);
            zaS += p[row * HH + jg];
            aaS += p[(8 + row) * HH + jg];
        }
        const float z = sigmoidf_(xz + zaS + bzv);
        const float e = __expf(tanhf(xa + aaS) * vav);
        es[row * 64 + jj]  = e;
        ehs[row * 64 + jj] = e * h;
        __syncthreads();

        // partial softmax sums: warp w (<8) reduces row w over 64 local cols
        if (tid < 256) {
            const int w = tid >> 5, lane = tid & 31;
            float se = es[w * 64 + lane] + es[w * 64 + 32 + lane];
#pragma unroll
            for (int o = 16; o > 0; o >>= 1) se += __shfl_xor_sync(0xffffffffu, se, o);
            if (lane == 0) g_pS[(g * 4 + r) * 8 + w] = se;
        }

        // ======== stage B: partial GEMV of e*h over my k quarter ========
        unsigned long long dd[8];
#pragma unroll
        for (int q = 0; q < 8; ++q) dd[q] = 0ull;
#pragma unroll
        for (int q = 0; q < 8; ++q) {
            ulonglong2 uh = Uh2[(kqb + q) * 256 + jq];
            const float* eb = ehs + khalf * 32 + q * 4;
#pragma unroll
            for (int rr = 0; rr < 8; ++rr) {
                ulonglong2 ek = *(const ulonglong2*)(eb + rr * 64);
                ffma2(dd[rr], ek.x, uh.x); ffma2(dd[rr], ek.y, uh.y);
            }
        }
#pragma unroll
        for (int rr = 0; rr < 8; ++rr) pB_my[rr * HH + jq] = ffold(dd[rr]);
        __syncthreads();
        if (tid == 0) st_release_u32(&flbase[r * (TT * 2) + 2 * t + 1], 1u);
        if (tid < NSL && tid != r) {
            const unsigned int* f = &flbase[tid * (TT * 2) + 2 * t + 1];
            while (ld_acquire_u32(f) == 0u) { }
        }
        __syncthreads();

        // ======== stage B finalize ========
        float d = 0.f;
#pragma unroll
        for (int c = 0; c < 8; ++c) {
            const float* p = g_pB + (size_t)((g * 4) * 2 + c) * (8 * HH);
            d += p[row * HH + jg];
        }
        float S = 0.f;
#pragma unroll
        for (int c = 0; c < 4; ++c) S += g_pS[(g * 4 + c) * 8 + row];

        const float ht = tanhf(xh + d / S + bhv);
        const float hn = h + z * (ht - h);

        out[((size_t)(b0 + row) * TT + t) * HH + jg] = hn;
        h = hn;
        hs[row * 64 + jj] = hn;
        __syncthreads();
    }

    // h_last appended after outputs [B,T,H]
    float* hl = out + (size_t)BB * TT * HH;
    hl[(size_t)(b0 + row) * HH + jg] = h;
}

// ---------------------------------------------------------------
// kernel_launch: zero flags -> reblock -> GEMM -> scan
// Inputs: x, W_z, U_z, b_z, W_a, U_a, v_a, W_h, U_h, b_h
// ---------------------------------------------------------------
extern "C" void kernel_launch(void* const* d_in, const int* in_sizes, int n_in,
                              void* d_out, int out_size) {
    const float* x  = (const float*)d_in[0];
    const float* Wz = (const float*)d_in[1];
    const float* Uz = (const float*)d_in[2];
    const float* bz = (const float*)d_in[3];
    const float* Wa = (const float*)d_in[4];
    const float* Ua = (const float*)d_in[5];
    const float* va = (const float*)d_in[6];
    const float* Wh = (const float*)d_in[7];
    const float* Uh = (const float*)d_in[8];
    const float* bh = (const float*)d_in[9];
    float* out = (float*)d_out;

    static bool attr_set = false;
    if (!attr_set) {
        cudaFuncSetAttribute(scan_kernel, cudaFuncAttributeMaxDynamicSharedMemorySize,
                             50688 * 4);
        attr_set = true;
    }

    zero_flags<<<(NG * NSL * TT * 2 + 255) / 256, 256>>>();
    reblock_U<<<(HH * HH + 255) / 256, 256>>>(Uz, Ua, Uh);

    dim3 grid_g((BB * TT) / 128, (3 * HH) / 128);
    proj_gemm<<<grid_g, 256>>>(x, Wz, Wa, Wh);

    scan_kernel<<<NG * NSL, 512, 50688 * 4>>>(bz, va, bh, out);
}